// round 1
// baseline (speedup 1.0000x reference)
#include <cuda_runtime.h>

#define BB 32
#define OO 64
#define MM 128
#define HH 4
#define EE 64
#define HE 256
#define EP 65   // padded row stride for context/memory tiles (bank-conflict-free)

__device__ __forceinline__ float tanh_approx(float x) {
    float r;
    asm("tanh.approx.f32 %0, %1;" : "=f"(r) : "f"(x));
    return r;
}

// smem layout (floats):
//   ctxS  [MM][EP]  = 8320
//   memS  [MM][EP]  = 8320
//   qS    [HE]      = 256   (reused as headsS after logits)
//   wS    [EE]      = 64
//   logS  [HH][MM]  = 512   (logits, then probs in-place)
//   redS  [512]     = 512   (reduction scratch)
#define SMEM_FLOATS (2*MM*EP + HE + EE + HH*MM + 512)

__global__ __launch_bounds__(512, 1) void attn_fused_kernel(
    const float* __restrict__ query,   // [B,O,E]
    const float* __restrict__ context, // [B,M,E]
    const float* __restrict__ memory,  // [B,M,E]
    const float* __restrict__ W_ch,    // [E, HE]
    const float* __restrict__ b_ch,    // [HE]
    const float* __restrict__ w_logit, // [E]
    const float* __restrict__ b_logit, // [1]
    const float* __restrict__ W_rh,    // [HE, E]
    const float* __restrict__ b_rh,    // [E]
    const float* __restrict__ temp,    // [1]
    float* __restrict__ out)           // [B,O,E]
{
    extern __shared__ float smem[];
    float* ctxS = smem;                 // [MM][EP]
    float* memS = ctxS + MM * EP;       // [MM][EP]
    float* qS   = memS + MM * EP;       // [HE]
    float* wS   = qS + HE;              // [EE]
    float* logS = wS + EE;              // [HH][MM]
    float* redS = logS + HH * MM;       // [512]

    __shared__ float qrowS[EE];

    const int t  = threadIdx.x;
    const int bx = blockIdx.x;
    const int b  = bx >> 6;   // / OO
    const int o  = bx & 63;   // % OO

    const float* qrow = query   + (size_t)(b * OO + o) * EE;
    const float* ctxG = context + (size_t)b * MM * EE;
    const float* memG = memory  + (size_t)b * MM * EE;

    // ---- stage context & memory tiles into padded smem ----
    #pragma unroll
    for (int i = t; i < MM * EE; i += 512) {
        int m = i >> 6, e = i & 63;
        ctxS[m * EP + e] = ctxG[i];
        memS[m * EP + e] = memG[i];
    }
    if (t < EE) {
        wS[t]    = w_logit[t];
        qrowS[t] = qrow[t];
    }
    __syncthreads();

    // ---- q projection: q[h,e] = query[b,o,:] @ W_ch + b_ch ----
    if (t < HE) {
        float acc = b_ch[t];
        #pragma unroll 16
        for (int k = 0; k < EE; k++)
            acc = fmaf(qrowS[k], W_ch[k * HE + t], acc);
        qS[t] = acc;
    }
    __syncthreads();

    // ---- logits[h][m] = (sum_e w[e]*tanh(ctx[m][e]+q[h][e]) + b_logit) / temp ----
    const float invtemp = 1.0f / temp[0];
    const float blog    = b_logit[0];
    {
        const int h = t >> 7;        // warp-uniform
        const int m = t & 127;
        const float* cr = ctxS + m * EP;   // conflict-free (EP=65)
        const float* qh = qS + h * EE;     // warp-uniform -> broadcast
        float acc = 0.0f;
        #pragma unroll 8
        for (int e = 0; e < EE; e++)
            acc = fmaf(wS[e], tanh_approx(cr[e] + qh[e]), acc);
        logS[h * MM + m] = (acc + blog) * invtemp;
    }
    __syncthreads();

    // ---- softmax over m, one warp per head ----
    {
        const int warp = t >> 5, lane = t & 31;
        if (warp < HH) {
            float* L = logS + warp * MM;
            float v0 = L[lane], v1 = L[lane + 32], v2 = L[lane + 64], v3 = L[lane + 96];
            float mx = fmaxf(fmaxf(v0, v1), fmaxf(v2, v3));
            #pragma unroll
            for (int s = 16; s; s >>= 1)
                mx = fmaxf(mx, __shfl_xor_sync(0xFFFFFFFFu, mx, s));
            float e0 = __expf(v0 - mx), e1 = __expf(v1 - mx);
            float e2 = __expf(v2 - mx), e3 = __expf(v3 - mx);
            float sm = e0 + e1 + e2 + e3;
            #pragma unroll
            for (int s = 16; s; s >>= 1)
                sm += __shfl_xor_sync(0xFFFFFFFFu, sm, s);
            float inv = 1.0f / sm;
            L[lane] = e0 * inv; L[lane + 32] = e1 * inv;
            L[lane + 64] = e2 * inv; L[lane + 96] = e3 * inv;
        }
    }
    __syncthreads();

    // ---- heads[h,e] = sum_m probs[h][m] * mem[m][e], split m over 2 halves ----
    {
        const int idx  = t & 255;   // h*64+e
        const int half = t >> 8;    // 0/1
        const int h = idx >> 6, e = idx & 63;
        const float* pr = logS + h * MM + half * 64;  // warp-uniform -> broadcast
        const float* mm = memS + (half * 64) * EP + e;
        float acc = 0.0f;
        #pragma unroll 8
        for (int m = 0; m < 64; m++)
            acc = fmaf(pr[m], mm[m * EP], acc);
        redS[t] = acc;
    }
    __syncthreads();

    // combine halves + leaky relu; reuse qS as heads storage
    float* headsS = qS;
    if (t < HE) {
        float v = redS[t] + redS[t + 256];
        headsS[t] = (v > 0.0f) ? v : 0.01f * v;
    }
    __syncthreads();

    // ---- out[e] = heads @ W_rh + b_rh; 8 partial slices of 32 k's ----
    {
        const int e    = t & 63;
        const int part = t >> 6;    // 0..7
        const float* wr = W_rh + (part * 32) * EE + e;
        const float* hs = headsS + part * 32;
        float acc = 0.0f;
        #pragma unroll 8
        for (int k = 0; k < 32; k++)
            acc = fmaf(hs[k], wr[k * EE], acc);
        redS[t] = acc;
    }
    __syncthreads();
    if (t < EE) {
        float v = redS[t]       + redS[t + 64]  + redS[t + 128] + redS[t + 192]
                + redS[t + 256] + redS[t + 320] + redS[t + 384] + redS[t + 448]
                + b_rh[t];
        out[(size_t)(b * OO + o) * EE + t] = v;
    }
}

extern "C" void kernel_launch(void* const* d_in, const int* in_sizes, int n_in,
                              void* d_out, int out_size) {
    const float* query   = (const float*)d_in[0];
    const float* context = (const float*)d_in[1];
    const float* memory  = (const float*)d_in[2];
    const float* W_ch    = (const float*)d_in[3];
    const float* b_ch    = (const float*)d_in[4];
    const float* w_logit = (const float*)d_in[5];
    const float* b_logit = (const float*)d_in[6];
    const float* W_rh    = (const float*)d_in[7];
    const float* b_rh    = (const float*)d_in[8];
    const float* temp    = (const float*)d_in[9];
    float* out = (float*)d_out;

    const size_t smem_bytes = SMEM_FLOATS * sizeof(float);
    cudaFuncSetAttribute(attn_fused_kernel,
                         cudaFuncAttributeMaxDynamicSharedMemorySize,
                         (int)smem_bytes);

    attn_fused_kernel<<<BB * OO, 512, smem_bytes>>>(
        query, context, memory, W_ch, b_ch, w_logit, b_logit, W_rh, b_rh, temp, out);
}

// round 2
// speedup vs baseline: 1.3767x; 1.3767x over previous
#include <cuda_runtime.h>

#define BB 32
#define OO 64
#define MM 128
#define HH 4
#define EE 64
#define HE 256
#define OB 4          // o's per block
#define EP 68         // padded row stride (floats): lane stride ≡ 4 banks -> LDS.128 conflict-free
#define EP4 17        // EP/4 (float4 row stride)

__device__ __forceinline__ float tanh_approx(float x) {
    float r;
    asm("tanh.approx.f32 %0, %1;" : "=f"(r) : "f"(x));
    return r;
}

// smem layout (floats):
//  ctxS [MM][EP]          = 8704
//  memS [MM][EP]          = 8704
//  qS   [OB][HE]          = 1024
//  wS   [EE]              = 64
//  qrowS[OB][EE]          = 256
//  probS[OB][HH*MM]       = 2048   (logits -> probs in place)
//  redS [1024]            = 1024
//  headsS[OB][HE]         = 1024
#define SMEM_FLOATS (2*MM*EP + OB*HE + EE + OB*EE + OB*HH*MM + 1024 + OB*HE)

__global__ __launch_bounds__(512, 2) void attn_fused2_kernel(
    const float* __restrict__ query,   // [B,O,E]
    const float* __restrict__ context, // [B,M,E]
    const float* __restrict__ memory,  // [B,M,E]
    const float* __restrict__ W_ch,    // [E, HE]
    const float* __restrict__ b_ch,    // [HE]
    const float* __restrict__ w_logit, // [E]
    const float* __restrict__ b_logit, // [1]
    const float* __restrict__ W_rh,    // [HE, E]
    const float* __restrict__ b_rh,    // [E]
    const float* __restrict__ temp,    // [1]
    float* __restrict__ out)           // [B,O,E]
{
    extern __shared__ float smem[];
    float* ctxS   = smem;                     // [MM][EP]
    float* memS   = ctxS + MM * EP;           // [MM][EP]
    float* qS     = memS + MM * EP;           // [OB][HE]
    float* wS     = qS + OB * HE;             // [EE]
    float* qrowS  = wS + EE;                  // [OB][EE]
    float* probS  = qrowS + OB * EE;          // [OB][HH*MM]
    float* redS   = probS + OB * HH * MM;     // [1024]
    float* headsS = redS + 1024;              // [OB][HE]

    const int t  = threadIdx.x;
    const int b  = blockIdx.x >> 4;           // / (OO/OB)
    const int o0 = (blockIdx.x & 15) * OB;

    const float4* ctxG4 = (const float4*)(context + (size_t)b * MM * EE);
    const float4* memG4 = (const float4*)(memory  + (size_t)b * MM * EE);
    float4* ctxS4 = (float4*)ctxS;
    float4* memS4 = (float4*)memS;

    // ---- stage context & memory tiles (float4, padded) ----
    #pragma unroll
    for (int i = t; i < MM * EE / 4; i += 512) {
        int m = i >> 4, j = i & 15;
        ctxS4[m * EP4 + j] = ctxG4[i];
        memS4[m * EP4 + j] = memG4[i];
    }
    if (t < EE) wS[t] = w_logit[t];
    if (t < OB * EE) {
        int o = t >> 6, e = t & 63;
        qrowS[t] = query[(size_t)(b * OO + o0 + o) * EE + e];
    }
    __syncthreads();

    // ---- q projection: 256 threads, each col computes OB outputs ----
    if (t < HE) {
        float bc = b_ch[t];
        float a0 = bc, a1 = bc, a2 = bc, a3 = bc;
        #pragma unroll 8
        for (int k = 0; k < EE; k++) {
            float w = W_ch[k * HE + t];
            a0 = fmaf(qrowS[k],        w, a0);
            a1 = fmaf(qrowS[64 + k],   w, a1);
            a2 = fmaf(qrowS[128 + k],  w, a2);
            a3 = fmaf(qrowS[192 + k],  w, a3);
        }
        qS[t]          = a0;
        qS[HE + t]     = a1;
        qS[2 * HE + t] = a2;
        qS[3 * HE + t] = a3;
    }
    __syncthreads();

    // ---- logits: thread=(h,m), 4 o-accumulators, float4 smem reads ----
    const float invtemp = 1.0f / temp[0];
    const float blog    = b_logit[0];
    {
        const int h = t >> 7;                 // warp-uniform
        const int m = t & 127;
        const float4* cr4 = ctxS4 + m * EP4;          // conflict-free LDS.128
        const float4* w4p = (const float4*)wS;        // broadcast
        const float4* q0p = (const float4*)(qS)           + h * 16;
        const float4* q1p = (const float4*)(qS + HE)      + h * 16;
        const float4* q2p = (const float4*)(qS + 2 * HE)  + h * 16;
        const float4* q3p = (const float4*)(qS + 3 * HE)  + h * 16;
        float a0 = 0.f, a1 = 0.f, a2 = 0.f, a3 = 0.f;
        #pragma unroll
        for (int j = 0; j < 16; j++) {
            float4 w4 = w4p[j];
            float4 c4 = cr4[j];
            float4 q0 = q0p[j], q1 = q1p[j], q2 = q2p[j], q3 = q3p[j];
            a0 = fmaf(w4.x, tanh_approx(c4.x + q0.x), a0);
            a1 = fmaf(w4.x, tanh_approx(c4.x + q1.x), a1);
            a2 = fmaf(w4.x, tanh_approx(c4.x + q2.x), a2);
            a3 = fmaf(w4.x, tanh_approx(c4.x + q3.x), a3);
            a0 = fmaf(w4.y, tanh_approx(c4.y + q0.y), a0);
            a1 = fmaf(w4.y, tanh_approx(c4.y + q1.y), a1);
            a2 = fmaf(w4.y, tanh_approx(c4.y + q2.y), a2);
            a3 = fmaf(w4.y, tanh_approx(c4.y + q3.y), a3);
            a0 = fmaf(w4.z, tanh_approx(c4.z + q0.z), a0);
            a1 = fmaf(w4.z, tanh_approx(c4.z + q1.z), a1);
            a2 = fmaf(w4.z, tanh_approx(c4.z + q2.z), a2);
            a3 = fmaf(w4.z, tanh_approx(c4.z + q3.z), a3);
            a0 = fmaf(w4.w, tanh_approx(c4.w + q0.w), a0);
            a1 = fmaf(w4.w, tanh_approx(c4.w + q1.w), a1);
            a2 = fmaf(w4.w, tanh_approx(c4.w + q2.w), a2);
            a3 = fmaf(w4.w, tanh_approx(c4.w + q3.w), a3);
        }
        probS[0 * 512 + h * MM + m] = (a0 + blog) * invtemp;
        probS[1 * 512 + h * MM + m] = (a1 + blog) * invtemp;
        probS[2 * 512 + h * MM + m] = (a2 + blog) * invtemp;
        probS[3 * 512 + h * MM + m] = (a3 + blog) * invtemp;
    }
    __syncthreads();

    // ---- softmax over m: 16 warps, warp=(o,h) ----
    {
        const int warp = t >> 5, lane = t & 31;
        float* L = probS + (warp >> 2) * 512 + (warp & 3) * MM;
        float v0 = L[lane], v1 = L[lane + 32], v2 = L[lane + 64], v3 = L[lane + 96];
        float mx = fmaxf(fmaxf(v0, v1), fmaxf(v2, v3));
        #pragma unroll
        for (int s = 16; s; s >>= 1)
            mx = fmaxf(mx, __shfl_xor_sync(0xFFFFFFFFu, mx, s));
        float e0 = __expf(v0 - mx), e1 = __expf(v1 - mx);
        float e2 = __expf(v2 - mx), e3 = __expf(v3 - mx);
        float sm = e0 + e1 + e2 + e3;
        #pragma unroll
        for (int s = 16; s; s >>= 1)
            sm += __shfl_xor_sync(0xFFFFFFFFu, sm, s);
        float inv = 1.0f / sm;
        L[lane]      = e0 * inv; L[lane + 32] = e1 * inv;
        L[lane + 64] = e2 * inv; L[lane + 96] = e3 * inv;
    }
    __syncthreads();

    // ---- heads[o][h][e] = sum_m probs[o][h][m] * mem[m][e]; float4 over e ----
    {
        const int part = t >> 8;              // m-half
        const int idx  = t & 255;             // o*64 + h*16 + j
        const int o    = idx >> 6;
        const int h    = (idx >> 4) & 3;
        const int j    = idx & 15;
        const float*  pr  = probS + o * 512 + h * MM + part * 64;
        const float4* mm4 = memS4 + (part * 64) * EP4 + j;
        float4 acc = make_float4(0.f, 0.f, 0.f, 0.f);
        #pragma unroll 8
        for (int m = 0; m < 64; m++) {
            float  p = pr[m];
            float4 v = mm4[m * EP4];
            acc.x = fmaf(p, v.x, acc.x);
            acc.y = fmaf(p, v.y, acc.y);
            acc.z = fmaf(p, v.z, acc.z);
            acc.w = fmaf(p, v.w, acc.w);
        }
        if (part) ((float4*)redS)[idx] = acc;
        __syncthreads();
        if (!part) {
            float4 r = ((float4*)redS)[idx];
            float vx = acc.x + r.x, vy = acc.y + r.y;
            float vz = acc.z + r.z, vw = acc.w + r.w;
            float4 hd;
            hd.x = (vx > 0.f) ? vx : 0.01f * vx;
            hd.y = (vy > 0.f) ? vy : 0.01f * vy;
            hd.z = (vz > 0.f) ? vz : 0.01f * vz;
            hd.w = (vw > 0.f) ? vw : 0.01f * vw;
            ((float4*)headsS)[idx] = hd;      // headsS[o][h*64 + 4j + c]
        }
    }
    __syncthreads();

    // ---- out[o][e] = heads[o] @ W_rh + b_rh; k split in 2 halves ----
    {
        const int part = t >> 8;              // k-half
        const int o    = (t >> 6) & 3;        // warp-uniform
        const int e    = t & 63;
        const float* hs = headsS + o * HE + part * 128;  // broadcast
        const float* wr = W_rh + (part * 128) * EE + e;  // coalesced, L2-resident
        float acc = 0.f;
        #pragma unroll 8
        for (int k = 0; k < 128; k++)
            acc = fmaf(hs[k], wr[k * EE], acc);
        redS[t] = acc;
    }
    __syncthreads();
    if (t < 256) {
        const int o = t >> 6, e = t & 63;
        float v = redS[t] + redS[t + 256] + b_rh[e];
        out[(size_t)(b * OO + o0 + o) * EE + e] = v;
    }
}

extern "C" void kernel_launch(void* const* d_in, const int* in_sizes, int n_in,
                              void* d_out, int out_size) {
    const float* query   = (const float*)d_in[0];
    const float* context = (const float*)d_in[1];
    const float* memory  = (const float*)d_in[2];
    const float* W_ch    = (const float*)d_in[3];
    const float* b_ch    = (const float*)d_in[4];
    const float* w_logit = (const float*)d_in[5];
    const float* b_logit = (const float*)d_in[6];
    const float* W_rh    = (const float*)d_in[7];
    const float* b_rh    = (const float*)d_in[8];
    const float* temp    = (const float*)d_in[9];
    float* out = (float*)d_out;

    const size_t smem_bytes = SMEM_FLOATS * sizeof(float);
    cudaFuncSetAttribute(attn_fused2_kernel,
                         cudaFuncAttributeMaxDynamicSharedMemorySize,
                         (int)smem_bytes);

    attn_fused2_kernel<<<BB * (OO / OB), 512, smem_bytes>>>(
        query, context, memory, W_ch, b_ch, w_logit, b_logit, W_rh, b_rh, temp, out);
}